// round 3
// baseline (speedup 1.0000x reference)
#include <cuda_runtime.h>

#define B_TOT 2048
#define IN    256
#define INP1  257
#define OUT   256
#define BT    256   // b-rows per block == threads per block
#define OPB   4     // o-columns per block
#define CHUNK 32    // i-chunk staged in smem

__global__ __launch_bounds__(BT) void skan_kernel(
    const float* __restrict__ x,       // [B_TOT, IN]
    const float* __restrict__ weight,  // [OUT, INP1]
    const float* __restrict__ w,       // [OUT, INP1]
    float* __restrict__ out)           // [B_TOT, OUT]
{
    // x chunk, transposed + padded: xs[i][b] so compute reads (stride-1 across
    // lanes) and transpose writes ((i*257+row)%32 covers all banks) are
    // conflict-free.
    __shared__ float xs[CHUNK][BT + 1];
    __shared__ float wt_s[OPB][INP1];
    __shared__ float ww_s[OPB][INP1];

    const int tid    = threadIdx.x;
    const int b_base = blockIdx.x * BT;
    const int o_base = blockIdx.y * OPB;

    // Stage this block's weight / w rows once (read warp-uniform afterwards ->
    // LDS broadcast, zero conflicts).
    for (int k = tid; k < OPB * INP1; k += BT) {
        int j = k / INP1;
        int i = k - j * INP1;
        wt_s[j][i] = weight[(o_base + j) * INP1 + i];
        ww_s[j][i] = w[(o_base + j) * INP1 + i];
    }
    __syncthreads();

    // Bias column (x_ext[:,256] == 1) is constant per o: fold into the init.
    float acc[OPB];
#pragma unroll
    for (int j = 0; j < OPB; ++j)
        acc[j] = wt_s[j][IN] * __sinf(ww_s[j][IN]);

    const int lrow = tid >> 5;  // warp id 0..7  -> row within a pass
    const int lcol = tid & 31;  // lane          -> column (contiguous gmem)

    for (int c = 0; c < IN / CHUNK; ++c) {
        __syncthreads();  // WAR guard on xs from previous iteration
        // Coalesced transpose-load: each pass, warp W loads row (p*8+W)'s
        // 32-float (128B) chunk; 32 passes cover all 256 rows. Unrolled so the
        // 32 LDGs are in flight together (MLP).
#pragma unroll
        for (int p = 0; p < BT / 8; ++p) {
            int row = p * 8 + lrow;
            xs[lcol][row] = x[(size_t)(b_base + row) * IN + c * CHUNK + lcol];
        }
        __syncthreads();

#pragma unroll 8
        for (int i = 0; i < CHUNK; ++i) {
            float xv = xs[i][tid];          // stride-1 across lanes
            int   gi = c * CHUNK + i;
#pragma unroll
            for (int j = 0; j < OPB; ++j)   // 4 sins per x load
                acc[j] = fmaf(wt_s[j][gi], __sinf(ww_s[j][gi] * xv), acc[j]);
        }
    }

    // o_base is a multiple of 4 and acc[0..3] are consecutive o's -> one
    // STG.128 per thread.
    float4 v = make_float4(acc[0], acc[1], acc[2], acc[3]);
    *reinterpret_cast<float4*>(out + (size_t)(b_base + tid) * OUT + o_base) = v;
}

extern "C" void kernel_launch(void* const* d_in, const int* in_sizes, int n_in,
                              void* d_out, int out_size) {
    const float* x      = (const float*)d_in[0];
    const float* weight = (const float*)d_in[1];
    const float* w      = (const float*)d_in[2];
    float* out          = (float*)d_out;

    dim3 grid(B_TOT / BT, OUT / OPB);  // (8, 64) = 512 CTAs
    skan_kernel<<<grid, BT>>>(x, weight, w, out);
}

// round 4
// speedup vs baseline: 1.0759x; 1.0759x over previous
#include <cuda_runtime.h>

#define B_TOT 2048
#define IN    256
#define INP1  257
#define OUT   256
#define BT    256   // b-rows per block == threads per block
#define OPB   4     // o-columns per block
#define CHUNK 32    // i-chunk staged in smem
#define WROW  516   // interleaved (w,weight) row: 2*257=514, padded to mult of 4 (16B rows)

__global__ __launch_bounds__(BT) void skan_kernel(
    const float* __restrict__ x,       // [B_TOT, IN]
    const float* __restrict__ weight,  // [OUT, INP1]
    const float* __restrict__ w,       // [OUT, INP1]
    float* __restrict__ out)           // [B_TOT, OUT]
{
    // x chunk, transposed + padded: xs[i][b] -> compute reads stride-1 across
    // lanes, transpose writes cover all banks.
    __shared__ float xs[CHUNK][BT + 1];
    // Interleaved pairs: wwt[j][2*i] = w[o,i], wwt[j][2*i+1] = weight[o,i].
    // Row stride 516 floats = 2064B (16B multiple) so float4 reads at even i
    // are aligned -> one broadcast LDS.128 yields 2 sins' worth of operands.
    __shared__ float wwt[OPB][WROW];

    const int tid    = threadIdx.x;
    const int b_base = blockIdx.x * BT;
    const int o_base = blockIdx.y * OPB;

    // Stage interleaved (w, weight) rows once.
    for (int k = tid; k < OPB * INP1; k += BT) {
        int j = k / INP1;
        int i = k - j * INP1;
        wwt[j][2 * i]     = w[(o_base + j) * INP1 + i];
        wwt[j][2 * i + 1] = weight[(o_base + j) * INP1 + i];
    }

    // Bias column (x_ext[:,256] == 1) is constant per o: fold into init.
    // Read straight from global (uniform, once, L2-hot).
    float acc[OPB];
#pragma unroll
    for (int j = 0; j < OPB; ++j) {
        float wb  = w[(o_base + j) * INP1 + IN];
        float wtb = weight[(o_base + j) * INP1 + IN];
        acc[j] = wtb * __sinf(wb);
    }
    __syncthreads();

    const int lrow = tid >> 5;  // warp id 0..7
    const int lcol = tid & 31;  // lane -> contiguous gmem column

    for (int c = 0; c < IN / CHUNK; ++c) {
        if (c) __syncthreads();  // WAR guard on xs
        // Coalesced transpose-load: 32 passes of 128B rows, all in flight.
#pragma unroll
        for (int p = 0; p < BT / 8; ++p) {
            int row = p * 8 + lrow;
            xs[lcol][row] = x[(size_t)(b_base + row) * IN + c * CHUNK + lcol];
        }
        __syncthreads();

#pragma unroll 8
        for (int i = 0; i < CHUNK; i += 2) {
            float xv0 = xs[i][tid];
            float xv1 = xs[i + 1][tid];
            int   gi  = c * CHUNK + i;
#pragma unroll
            for (int j = 0; j < OPB; ++j) {
                // (w_i, wt_i, w_{i+1}, wt_{i+1}) in one broadcast LDS.128
                float4 p = *reinterpret_cast<const float4*>(&wwt[j][2 * gi]);
                acc[j] = fmaf(p.y, __sinf(p.x * xv0), acc[j]);
                acc[j] = fmaf(p.w, __sinf(p.z * xv1), acc[j]);
            }
        }
    }

    // acc[0..3] are consecutive o's at a 16B-aligned address -> one STG.128.
    float4 v = make_float4(acc[0], acc[1], acc[2], acc[3]);
    *reinterpret_cast<float4*>(out + (size_t)(b_base + tid) * OUT + o_base) = v;
}

extern "C" void kernel_launch(void* const* d_in, const int* in_sizes, int n_in,
                              void* d_out, int out_size) {
    const float* x      = (const float*)d_in[0];
    const float* weight = (const float*)d_in[1];
    const float* w      = (const float*)d_in[2];
    float* out          = (float*)d_out;

    dim3 grid(B_TOT / BT, OUT / OPB);  // (8, 64) = 512 CTAs
    skan_kernel<<<grid, BT>>>(x, weight, w, out);
}

// round 5
// speedup vs baseline: 1.2911x; 1.2000x over previous
#include <cuda_runtime.h>

#define B_TOT 2048
#define IN    256
#define INP1  257
#define OUT   256

#define THREADS 128   // 4 warps
#define NWARP   4
#define OBLK    32    // o's per block: lane -> o
#define BW      4     // b's per warp
#define BBLK    (NWARP * BW)   // 16 b's per block
#define CHUNK   32    // i's staged per stage
#define NCHUNK  (IN / CHUNK)   // 8

__global__ __launch_bounds__(THREADS) void skan_kernel(
    const float* __restrict__ x,       // [B_TOT, IN]
    const float* __restrict__ weight,  // [OUT, INP1]
    const float* __restrict__ w,       // [OUT, INP1]
    float* __restrict__ out)           // [B_TOT, OUT]
{
    // [buf][i][o] for weights (per-lane read: lane -> o, conflict-free with +1 pad)
    __shared__ float ws [2][CHUNK][OBLK + 1];
    __shared__ float wts[2][CHUNK][OBLK + 1];
    // [buf][b][i] for x (read is warp-uniform broadcast; layout only matters for STS)
    __shared__ float xsm[2][BBLK][CHUNK + 1];

    const int tid    = threadIdx.x;
    const int lane   = tid & 31;
    const int wid    = tid >> 5;
    const int o_base = blockIdx.y * OBLK;
    const int o      = o_base + lane;        // this thread's output column
    const int b_base = blockIdx.x * BBLK;

    // Bias column (x_ext[:,256] == 1): constant per o, same for every b this
    // thread owns -> fold into accumulator init. One-time uncoalesced LDG, fine.
    float acc[BW];
    {
        float wb  = w[(size_t)o * INP1 + IN];
        float wtb = weight[(size_t)o * INP1 + IN];
        float bi  = wtb * __sinf(wb);
#pragma unroll
        for (int b = 0; b < BW; ++b) acc[b] = bi;
    }

    // Register prefetch buffers for one chunk:
    //   weights: 32 o-rows x 32 i-cols = 1024 elems / 128 thr = 8 per thread
    //   x:       16 b-rows x 32 i-cols =  512 elems / 128 thr = 4 per thread
    float pw[8], pwt[8], px[4];

    // ---- prefetch chunk 0 (coalesced: lane -> contiguous i) ----
#pragma unroll
    for (int p = 0; p < 8; ++p) {
        int r = p * NWARP + wid;  // o row 0..31
        pw [p] = w     [(size_t)(o_base + r) * INP1 + lane];
        pwt[p] = weight[(size_t)(o_base + r) * INP1 + lane];
    }
#pragma unroll
    for (int p = 0; p < BW; ++p) {
        int r = p * NWARP + wid;  // b row 0..15
        px[p] = x[(size_t)(b_base + r) * IN + lane];
    }

    for (int c = 0; c < NCHUNK; ++c) {
        const int buf = c & 1;

        // Store prefetched chunk into smem (transposed for weights).
        // ws[buf][i=lane][o=r]: bank = lane*33 + r -> distinct across lanes.
#pragma unroll
        for (int p = 0; p < 8; ++p) {
            int r = p * NWARP + wid;
            ws [buf][lane][r] = pw [p];
            wts[buf][lane][r] = pwt[p];
        }
#pragma unroll
        for (int p = 0; p < BW; ++p) {
            int r = p * NWARP + wid;
            xsm[buf][r][lane] = px[p];
        }
        __syncthreads();

        // Issue next chunk's LDGs now; their latency hides under compute below.
        if (c + 1 < NCHUNK) {
            int ci = (c + 1) * CHUNK + lane;
#pragma unroll
            for (int p = 0; p < 8; ++p) {
                int r = p * NWARP + wid;
                pw [p] = w     [(size_t)(o_base + r) * INP1 + ci];
                pwt[p] = weight[(size_t)(o_base + r) * INP1 + ci];
            }
#pragma unroll
            for (int p = 0; p < BW; ++p) {
                int r = p * NWARP + wid;
                px[p] = x[(size_t)(b_base + r) * IN + ci];
            }
        }

        // Compute: weights per-lane (reused across BW b's), x broadcast
        // (one LDS serves all 32 lanes/o's).
#pragma unroll 8
        for (int i = 0; i < CHUNK; ++i) {
            float wv  = ws [buf][i][lane];
            float wtv = wts[buf][i][lane];
#pragma unroll
            for (int b = 0; b < BW; ++b) {
                float xv = xsm[buf][wid * BW + b][i];  // warp-uniform broadcast
                acc[b] = fmaf(wtv, __sinf(wv * xv), acc[b]);
            }
        }
        // No trailing sync needed: next iteration writes the OTHER buffer, and
        // reuse of THIS buffer (c+2) is fenced by c+1's __syncthreads.
    }

    // Store: per b, warp writes 32 consecutive o's -> coalesced 128B STG.
#pragma unroll
    for (int b = 0; b < BW; ++b) {
        int bb = b_base + wid * BW + b;
        out[(size_t)bb * OUT + o] = acc[b];
    }
}

extern "C" void kernel_launch(void* const* d_in, const int* in_sizes, int n_in,
                              void* d_out, int out_size) {
    const float* x      = (const float*)d_in[0];
    const float* weight = (const float*)d_in[1];
    const float* w      = (const float*)d_in[2];
    float* out          = (float*)d_out;

    dim3 grid(B_TOT / BBLK, OUT / OBLK);  // (128, 8) = 1024 CTAs
    skan_kernel<<<grid, THREADS>>>(x, weight, w, out);
}